// round 15
// baseline (speedup 1.0000x reference)
#include <cuda_runtime.h>
#include <stdint.h>

// Dataset-fixed shapes. Harness delivers uint8 arrays EXPANDED to one value
// 0..255 per 32-bit element (int32 or float32 — uniform-detected at runtime).
//   weights: 524288 elems, flip: 16777216 elems (32 layers x 524288)
//   out: 524289 f32 = new_weights byte values ++ update_ratio  [or 524288 i32]
#define WORDS       131072            // packed uint32 words
#define LAYERS      32
#define TOTAL_BITS  4194304
#define LAYER_U4    131072            // uint4 per layer
#define FLIP_ELEMS  16777216
#define W_ELEMS     524288
#define NBLK        512               // exact fit: 512*256 threads = 131072 words
#define NTHR        256
#define NCHUNK      8                 // 8 chunks x 4 layers = 32 layers

// Monotonic counters (graph-replay-safe: each run adds exactly NBLK; target is
// the next multiple of NBLK). Zero-initialized at module load.
__device__ unsigned int g_arrive = 0;
__device__ unsigned int g_done   = 0;
__device__ unsigned int g_cnt_part[NBLK];
__device__ unsigned int g_mask_part[NBLK];

// 4 expanded elements -> one packed byte word (elem k -> byte k)
__device__ __forceinline__ uint32_t pack4i(uint4 v) {   // int32-expanded path
    return __byte_perm(__byte_perm(v.x, v.y, 0x0040),
                       __byte_perm(v.z, v.w, 0x0040), 0x5410);
}
__device__ __forceinline__ uint32_t pack4f(uint4 v) {   // float32-expanded path
    uint32_t b0 = (uint32_t)__uint_as_float(v.x), b1 = (uint32_t)__uint_as_float(v.y);
    uint32_t b2 = (uint32_t)__uint_as_float(v.z), b3 = (uint32_t)__uint_as_float(v.w);
    return __byte_perm(__byte_perm(b0, b1, 0x0040),
                       __byte_perm(b2, b3, 0x0040), 0x5410);
}

// Full adder on bit-planes. 2 LOP3s.
__device__ __forceinline__ void CSA(uint32_t& h, uint32_t& l,
                                    uint32_t a, uint32_t b, uint32_t c) {
    uint32_t u = a ^ b;
    h = (a & b) | (u & c);
    l = u ^ c;
}

// Add 4 packed words into bit-plane accumulators s[0..5]. ~14 LOP3.
__device__ __forceinline__ void acc4(uint32_t* s, uint32_t p0, uint32_t p1,
                                     uint32_t p2, uint32_t p3) {
    uint32_t c1, x1;
    CSA(c1, x1, p0, p1, p2);
    uint32_t ones = x1 ^ p3, c2 = x1 & p3;
    uint32_t twos = c1 ^ c2, fours = c1 & c2;
    uint32_t k1 = s[0] & ones;  s[0] ^= ones;                 // weight 1
    uint32_t k2; CSA(k2, s[1], s[1], k1, twos);               // weight 2
    uint32_t k3; CSA(k3, s[2], s[2], k2, fours);              // weight 4
    uint32_t k4 = s[3] & k3;    s[3] ^= k3;                   // weight 8
    uint32_t k5 = s[4] & k4;    s[4] ^= k4;                   // weight 16
    s[5] ^= k5;                                               // weight 32
}

// Consume one 4-layer buffer into the planes (uniform dtype branch)
__device__ __forceinline__ void consume(uint32_t* s, bool isf,
                                        uint4 v0, uint4 v1, uint4 v2, uint4 v3) {
    if (isf) acc4(s, pack4f(v0), pack4f(v1), pack4f(v2), pack4f(v3));
    else     acc4(s, pack4i(v0), pack4i(v1), pack4i(v2), pack4i(v3));
}

#define LOAD4(b0, b1, b2, b3, ch)                                   \
    do {                                                            \
        const size_t _base = (size_t)(ch) * 4 * LAYER_U4;           \
        b0 = bp[_base + (size_t)0 * LAYER_U4];                      \
        b1 = bp[_base + (size_t)1 * LAYER_U4];                      \
        b2 = bp[_base + (size_t)2 * LAYER_U4];                      \
        b3 = bp[_base + (size_t)3 * LAYER_U4];                      \
    } while (0)

__global__ void __launch_bounds__(NTHR, 4) k_fused(
    const uint4* __restrict__ flip4,
    const uint4* __restrict__ weights4,
    const float* __restrict__ vpm,
    float* __restrict__ outf,
    int*  __restrict__ outi,
    int as_float)
{
    __shared__ unsigned int red[8];
    __shared__ unsigned int sh;

    const int tid  = threadIdx.x;
    const int warp = tid >> 5;
    const int lane = tid & 31;
    const int w    = blockIdx.x * NTHR + tid;   // packed word owned by thread
    const uint4* __restrict__ bp = flip4 + w;

    // Uniform dtype detect: int32 0..255 never sets bits >= 9; float32
    // encodings of values >= 1.0 do.
    if (tid == 0) {
        const uint32_t* r = (const uint32_t*)flip4;
        uint32_t o = r[0] | r[1] | r[2] | r[3] | r[4] | r[5] | r[6] | r[7];
        sh = (o >> 9) ? 1u : 0u;
    }

    // 3-buffer rotation: 12 LDG.128 in flight per thread in steady state.
    uint4 x0, x1, x2, x3, y0, y1, y2, y3, z0, z1, z2, z3;
    LOAD4(x0, x1, x2, x3, 0);
    LOAD4(y0, y1, y2, y3, 1);
    LOAD4(z0, z1, z2, z3, 2);

    __syncthreads();
    const bool isf = (sh != 0);
    __syncthreads();                            // sh reused later

    // ---- Phase 1: software-pipelined bit-sliced popcount of 32 layers ----
    // Rotate X/Y/Z over chunks; consume chunk i, refill its buffer with
    // chunk i+3. WAR register renaming keeps >=8-12 LDG.128 outstanding.
    uint32_t s[6] = {0, 0, 0, 0, 0, 0};
    #pragma unroll
    for (int ch = 0; ch < NCHUNK; ch += 3) {
        consume(s, isf, x0, x1, x2, x3);
        if (ch + 3 < NCHUNK) LOAD4(x0, x1, x2, x3, ch + 3);
        if (ch + 1 < NCHUNK) {
            consume(s, isf, y0, y1, y2, y3);
            if (ch + 4 < NCHUNK) LOAD4(y0, y1, y2, y3, ch + 4);
        }
        if (ch + 2 < NCHUNK) {
            consume(s, isf, z0, z1, z2, z3);
            if (ch + 5 < NCHUNK) LOAD4(z0, z1, z2, z3, ch + 5);
        }
    }

    // Prefetch weights (overlaps the barrier wait)
    const uint4 wv = weights4[w];

    // This thread's vote total: sum_k 2^k * popc(s_k)
    unsigned lanesum = __popc(s[0]) + 2 * __popc(s[1]) + 4 * __popc(s[2])
                     + 8 * __popc(s[3]) + 16 * __popc(s[4]) + 32 * __popc(s[5]);
    #pragma unroll
    for (int k = 16; k; k >>= 1) lanesum += __shfl_xor_sync(0xFFFFFFFFu, lanesum, k);
    if (lane == 0) red[warp] = lanesum;
    __syncthreads();

    // ---- Grid barrier (replay-safe monotonic counter) ----
    if (tid == 0) {
        unsigned b = 0;
        #pragma unroll
        for (int i = 0; i < 8; i++) b += red[i];
        g_cnt_part[blockIdx.x] = b;
        __threadfence();
        const unsigned old = atomicAdd(&g_arrive, 1u);
        const unsigned target = (old / NBLK) * NBLK + NBLK;
        while (*(volatile unsigned int*)&g_arrive < target) __nanosleep(32);
        __threadfence();
    }
    __syncthreads();

    // ---- Global total -> threshold (single-pass gather) ----
    {
        unsigned t = g_cnt_part[tid] + g_cnt_part[tid + NTHR];
        #pragma unroll
        for (int k = 16; k; k >>= 1) t += __shfl_xor_sync(0xFFFFFFFFu, t, k);
        if (lane == 0) red[warp] = t;
        __syncthreads();
        if (tid == 0) {
            unsigned tt = 0;
            #pragma unroll
            for (int i = 0; i < 8; i++) tt += red[i];
            sh = tt;
        }
        __syncthreads();
    }
    const unsigned total = sh;
    // p = max(vote_p_max, mean/32); mask = votes > p*32; integer votes:
    //   votes > th <=> votes > floor(th)
    const float mean = (float)((double)total * (1.0 / (double)TOTAL_BITS));
    const float p    = fmaxf(vpm[0], mean * (1.0f / 32.0f));
    const unsigned tb = (unsigned)floorf(p * 32.0f);

    // ---- Bit-sliced compare count > tb : result IS the packed mask word ----
    uint32_t gt = 0, eq = 0xFFFFFFFFu;
    #pragma unroll
    for (int k = 5; k >= 0; k--) {
        const uint32_t tk = (uint32_t)(-(int)((tb >> k) & 1u));
        gt |= eq & s[k] & ~tk;
        eq &= ~(s[k] ^ tk);
    }
    const uint32_t mask  = gt;
    const uint32_t wword = isf ? pack4f(wv) : pack4i(wv);
    const uint32_t xw    = ~(mask ^ wword);     // bytewise XNOR

    if (as_float) {
        float4 o = { (float)( xw        & 0xFFu), (float)((xw >> 8)  & 0xFFu),
                     (float)((xw >> 16) & 0xFFu), (float)((xw >> 24) & 0xFFu) };
        ((float4*)outf)[w] = o;
    } else {
        int4 o = { (int)( xw        & 0xFFu), (int)((xw >> 8)  & 0xFFu),
                   (int)((xw >> 16) & 0xFFu), (int)((xw >> 24) & 0xFFu) };
        ((int4*)outi)[w] = o;
    }

    // ---- Mask popcount partials; last finisher writes the ratio ----
    unsigned mp = __popc(mask);
    #pragma unroll
    for (int k = 16; k; k >>= 1) mp += __shfl_xor_sync(0xFFFFFFFFu, mp, k);
    if (lane == 0) red[warp] = mp;
    __syncthreads();
    if (tid == 0) {
        unsigned b = 0;
        #pragma unroll
        for (int i = 0; i < 8; i++) b += red[i];
        g_mask_part[blockIdx.x] = b;
        __threadfence();
        const unsigned old = atomicAdd(&g_done, 1u);
        sh = ((old % NBLK) == NBLK - 1) ? 1u : 0u;
    }
    __syncthreads();
    if (sh) {
        __threadfence();
        unsigned t = g_mask_part[tid] + g_mask_part[tid + NTHR];
        #pragma unroll
        for (int k = 16; k; k >>= 1) t += __shfl_xor_sync(0xFFFFFFFFu, t, k);
        if (lane == 0) red[warp] = t;
        __syncthreads();
        if (tid == 0 && as_float) {
            unsigned tt = 0;
            #pragma unroll
            for (int i = 0; i < 8; i++) tt += red[i];
            outf[W_ELEMS] = (float)((double)tt * (1.0 / (double)TOTAL_BITS));
        }
    }
}

extern "C" void kernel_launch(void* const* d_in, const int* in_sizes, int n_in,
                              void* d_out, int out_size)
{
    // Bind by element count (expansion preserves counts).
    const uint4* weights4 = 0;
    const uint4* flip4    = 0;
    const float* vpm      = 0;
    for (int i = 0; i < n_in; i++) {
        if      (in_sizes[i] == FLIP_ELEMS) flip4    = (const uint4*)d_in[i];
        else if (in_sizes[i] == W_ELEMS)    weights4 = (const uint4*)d_in[i];
        else if (in_sizes[i] == 1)          vpm      = (const float*)d_in[i];
    }
    if (!weights4 || !flip4) {
        weights4 = (const uint4*)d_in[0];
        flip4    = (const uint4*)d_in[1];
        vpm      = (const float*)d_in[n_in - 1];
    }

    const int as_float = (out_size != W_ELEMS) ? 1 : 0;

    k_fused<<<NBLK, NTHR>>>(flip4, weights4, vpm,
                            (float*)d_out, (int*)d_out, as_float);
}

// round 16
// speedup vs baseline: 1.0173x; 1.0173x over previous
#include <cuda_runtime.h>
#include <stdint.h>

// Dataset-fixed shapes. Harness delivers uint8 arrays EXPANDED to one value
// 0..255 per 32-bit element (int32 or float32 — uniform-detected at runtime).
//   weights: 524288 elems, flip: 16777216 elems (32 layers x 524288)
//   out: 524289 f32 = new_weights byte values ++ update_ratio  [or 524288 i32]
#define WORDS       131072            // packed uint32 words
#define LAYERS      32
#define TOTAL_BITS  4194304
#define LAYER_U4    131072            // uint4 per layer
#define FLIP_ELEMS  16777216
#define W_ELEMS     524288
#define NBLK        512               // exact fit: 512*256 threads = 131072 words
#define NTHR        256
#define NCHUNK      8                 // 8 chunks x 4 layers = 32 layers

// Monotonic counters (graph-replay-safe: each run adds exactly NBLK; target is
// the next multiple of NBLK). Zero-initialized at module load.
__device__ unsigned int g_arrive = 0;
__device__ unsigned int g_done   = 0;
__device__ unsigned int g_cnt_part[NBLK];
__device__ unsigned int g_mask_part[NBLK];

// 4 expanded elements -> one packed byte word (elem k -> byte k)
__device__ __forceinline__ uint32_t pack4i(uint4 v) {   // int32-expanded path
    return __byte_perm(__byte_perm(v.x, v.y, 0x0040),
                       __byte_perm(v.z, v.w, 0x0040), 0x5410);
}
__device__ __forceinline__ uint32_t pack4f(uint4 v) {   // float32-expanded path
    uint32_t b0 = (uint32_t)__uint_as_float(v.x), b1 = (uint32_t)__uint_as_float(v.y);
    uint32_t b2 = (uint32_t)__uint_as_float(v.z), b3 = (uint32_t)__uint_as_float(v.w);
    return __byte_perm(__byte_perm(b0, b1, 0x0040),
                       __byte_perm(b2, b3, 0x0040), 0x5410);
}

// Full adder on bit-planes. 2 LOP3s.
__device__ __forceinline__ void CSA(uint32_t& h, uint32_t& l,
                                    uint32_t a, uint32_t b, uint32_t c) {
    uint32_t u = a ^ b;
    h = (a & b) | (u & c);
    l = u ^ c;
}

// Add 4 packed words into bit-plane accumulators s[0..5]. ~14 LOP3.
__device__ __forceinline__ void acc4(uint32_t* s, uint32_t p0, uint32_t p1,
                                     uint32_t p2, uint32_t p3) {
    uint32_t c1, x1;
    CSA(c1, x1, p0, p1, p2);
    uint32_t ones = x1 ^ p3, c2 = x1 & p3;
    uint32_t twos = c1 ^ c2, fours = c1 & c2;
    uint32_t k1 = s[0] & ones;  s[0] ^= ones;                 // weight 1
    uint32_t k2; CSA(k2, s[1], s[1], k1, twos);               // weight 2
    uint32_t k3; CSA(k3, s[2], s[2], k2, fours);              // weight 4
    uint32_t k4 = s[3] & k3;    s[3] ^= k3;                   // weight 8
    uint32_t k5 = s[4] & k4;    s[4] ^= k4;                   // weight 16
    s[5] ^= k5;                                               // weight 32
}

// Consume one 4-layer buffer into the planes (uniform dtype branch)
__device__ __forceinline__ void consume(uint32_t* s, bool isf,
                                        uint4 v0, uint4 v1, uint4 v2, uint4 v3) {
    if (isf) acc4(s, pack4f(v0), pack4f(v1), pack4f(v2), pack4f(v3));
    else     acc4(s, pack4i(v0), pack4i(v1), pack4i(v2), pack4i(v3));
}

#define LOAD4(b0, b1, b2, b3, ch)                                   \
    do {                                                            \
        const size_t _base = (size_t)(ch) * 4 * LAYER_U4;           \
        b0 = bp[_base + (size_t)0 * LAYER_U4];                      \
        b1 = bp[_base + (size_t)1 * LAYER_U4];                      \
        b2 = bp[_base + (size_t)2 * LAYER_U4];                      \
        b3 = bp[_base + (size_t)3 * LAYER_U4];                      \
    } while (0)

__global__ void __launch_bounds__(NTHR, 4) k_fused(
    const uint4* __restrict__ flip4,
    const uint4* __restrict__ weights4,
    const float* __restrict__ vpm,
    float* __restrict__ outf,
    int*  __restrict__ outi,
    int as_float)
{
    __shared__ unsigned int red[8];
    __shared__ unsigned int sh;

    const int tid  = threadIdx.x;
    const int warp = tid >> 5;
    const int lane = tid & 31;
    const int w    = blockIdx.x * NTHR + tid;   // packed word owned by thread
    const uint4* __restrict__ bp = flip4 + w;

    // Uniform dtype detect: int32 0..255 never sets bits >= 9; float32
    // encodings of values >= 1.0 do.
    if (tid == 0) {
        const uint32_t* r = (const uint32_t*)flip4;
        uint32_t o = r[0] | r[1] | r[2] | r[3] | r[4] | r[5] | r[6] | r[7];
        sh = (o >> 9) ? 1u : 0u;
    }

    // 3-buffer rotation: 12 LDG.128 in flight per thread in steady state.
    uint4 x0, x1, x2, x3, y0, y1, y2, y3, z0, z1, z2, z3;
    LOAD4(x0, x1, x2, x3, 0);
    LOAD4(y0, y1, y2, y3, 1);
    LOAD4(z0, z1, z2, z3, 2);

    __syncthreads();
    const bool isf = (sh != 0);
    __syncthreads();                            // sh reused later

    // ---- Phase 1: software-pipelined bit-sliced popcount of 32 layers ----
    // Rotate X/Y/Z over chunks; consume chunk i, refill its buffer with
    // chunk i+3. WAR register renaming keeps >=8-12 LDG.128 outstanding.
    uint32_t s[6] = {0, 0, 0, 0, 0, 0};
    #pragma unroll
    for (int ch = 0; ch < NCHUNK; ch += 3) {
        consume(s, isf, x0, x1, x2, x3);
        if (ch + 3 < NCHUNK) LOAD4(x0, x1, x2, x3, ch + 3);
        if (ch + 1 < NCHUNK) {
            consume(s, isf, y0, y1, y2, y3);
            if (ch + 4 < NCHUNK) LOAD4(y0, y1, y2, y3, ch + 4);
        }
        if (ch + 2 < NCHUNK) {
            consume(s, isf, z0, z1, z2, z3);
            if (ch + 5 < NCHUNK) LOAD4(z0, z1, z2, z3, ch + 5);
        }
    }

    // Prefetch weights (overlaps the barrier wait)
    const uint4 wv = weights4[w];

    // This thread's vote total: sum_k 2^k * popc(s_k)
    unsigned lanesum = __popc(s[0]) + 2 * __popc(s[1]) + 4 * __popc(s[2])
                     + 8 * __popc(s[3]) + 16 * __popc(s[4]) + 32 * __popc(s[5]);
    #pragma unroll
    for (int k = 16; k; k >>= 1) lanesum += __shfl_xor_sync(0xFFFFFFFFu, lanesum, k);
    if (lane == 0) red[warp] = lanesum;
    __syncthreads();

    // ---- Grid barrier (replay-safe monotonic counter) ----
    if (tid == 0) {
        unsigned b = 0;
        #pragma unroll
        for (int i = 0; i < 8; i++) b += red[i];
        g_cnt_part[blockIdx.x] = b;
        __threadfence();
        const unsigned old = atomicAdd(&g_arrive, 1u);
        const unsigned target = (old / NBLK) * NBLK + NBLK;
        while (*(volatile unsigned int*)&g_arrive < target) __nanosleep(32);
        __threadfence();
    }
    __syncthreads();

    // ---- Global total -> threshold (single-pass gather) ----
    {
        unsigned t = g_cnt_part[tid] + g_cnt_part[tid + NTHR];
        #pragma unroll
        for (int k = 16; k; k >>= 1) t += __shfl_xor_sync(0xFFFFFFFFu, t, k);
        if (lane == 0) red[warp] = t;
        __syncthreads();
        if (tid == 0) {
            unsigned tt = 0;
            #pragma unroll
            for (int i = 0; i < 8; i++) tt += red[i];
            sh = tt;
        }
        __syncthreads();
    }
    const unsigned total = sh;
    // p = max(vote_p_max, mean/32); mask = votes > p*32; integer votes:
    //   votes > th <=> votes > floor(th)
    const float mean = (float)((double)total * (1.0 / (double)TOTAL_BITS));
    const float p    = fmaxf(vpm[0], mean * (1.0f / 32.0f));
    const unsigned tb = (unsigned)floorf(p * 32.0f);

    // ---- Bit-sliced compare count > tb : result IS the packed mask word ----
    uint32_t gt = 0, eq = 0xFFFFFFFFu;
    #pragma unroll
    for (int k = 5; k >= 0; k--) {
        const uint32_t tk = (uint32_t)(-(int)((tb >> k) & 1u));
        gt |= eq & s[k] & ~tk;
        eq &= ~(s[k] ^ tk);
    }
    const uint32_t mask  = gt;
    const uint32_t wword = isf ? pack4f(wv) : pack4i(wv);
    const uint32_t xw    = ~(mask ^ wword);     // bytewise XNOR

    if (as_float) {
        float4 o = { (float)( xw        & 0xFFu), (float)((xw >> 8)  & 0xFFu),
                     (float)((xw >> 16) & 0xFFu), (float)((xw >> 24) & 0xFFu) };
        ((float4*)outf)[w] = o;
    } else {
        int4 o = { (int)( xw        & 0xFFu), (int)((xw >> 8)  & 0xFFu),
                   (int)((xw >> 16) & 0xFFu), (int)((xw >> 24) & 0xFFu) };
        ((int4*)outi)[w] = o;
    }

    // ---- Mask popcount partials; last finisher writes the ratio ----
    unsigned mp = __popc(mask);
    #pragma unroll
    for (int k = 16; k; k >>= 1) mp += __shfl_xor_sync(0xFFFFFFFFu, mp, k);
    if (lane == 0) red[warp] = mp;
    __syncthreads();
    if (tid == 0) {
        unsigned b = 0;
        #pragma unroll
        for (int i = 0; i < 8; i++) b += red[i];
        g_mask_part[blockIdx.x] = b;
        __threadfence();
        const unsigned old = atomicAdd(&g_done, 1u);
        sh = ((old % NBLK) == NBLK - 1) ? 1u : 0u;
    }
    __syncthreads();
    if (sh) {
        __threadfence();
        unsigned t = g_mask_part[tid] + g_mask_part[tid + NTHR];
        #pragma unroll
        for (int k = 16; k; k >>= 1) t += __shfl_xor_sync(0xFFFFFFFFu, t, k);
        if (lane == 0) red[warp] = t;
        __syncthreads();
        if (tid == 0 && as_float) {
            unsigned tt = 0;
            #pragma unroll
            for (int i = 0; i < 8; i++) tt += red[i];
            outf[W_ELEMS] = (float)((double)tt * (1.0 / (double)TOTAL_BITS));
        }
    }
}

extern "C" void kernel_launch(void* const* d_in, const int* in_sizes, int n_in,
                              void* d_out, int out_size)
{
    // Bind by element count (expansion preserves counts).
    const uint4* weights4 = 0;
    const uint4* flip4    = 0;
    const float* vpm      = 0;
    for (int i = 0; i < n_in; i++) {
        if      (in_sizes[i] == FLIP_ELEMS) flip4    = (const uint4*)d_in[i];
        else if (in_sizes[i] == W_ELEMS)    weights4 = (const uint4*)d_in[i];
        else if (in_sizes[i] == 1)          vpm      = (const float*)d_in[i];
    }
    if (!weights4 || !flip4) {
        weights4 = (const uint4*)d_in[0];
        flip4    = (const uint4*)d_in[1];
        vpm      = (const float*)d_in[n_in - 1];
    }

    const int as_float = (out_size != W_ELEMS) ? 1 : 0;

    k_fused<<<NBLK, NTHR>>>(flip4, weights4, vpm,
                            (float*)d_out, (int*)d_out, as_float);
}